// round 1
// baseline (speedup 1.0000x reference)
#include <cuda_runtime.h>
#include <cstdint>

// SpikeFP32Adder: the reference simulates an FP32 adder circuit with
// soft gates over {0,1} float "bits". Since inputs are exactly 0/1, every
// gate is exact boolean algebra -> replicate the circuit bit-exactly with
// integer ops.
//
// Bit layout per row (32 floats, MSB-first): [sign][exp b7..b0][mant b22..b0]
// __brev(__ballot) of lane j holding bit j yields the IEEE-style word:
//   sign = bit31, exp = bits[30:23], mant = bits[22:0].

__device__ __forceinline__ unsigned spike_fp32_add(unsigned ra, unsigned rb) {
    const unsigned sa = ra >> 31, sb = rb >> 31;
    const unsigned ea = (ra >> 23) & 0xFFu, eb = (rb >> 23) & 0xFFu;
    const unsigned ma = ra & 0x7FFFFFu,     mb = rb & 0x7FFFFFu;

    const unsigned ha = (ea != 0u) ? 1u : 0u;
    const unsigned hb = (eb != 0u) ? 1u : 0u;
    const unsigned eae = ea ? ea : 1u;              // e_eff (subnormal -> 1)
    const unsigned ebe = eb ? eb : 1u;

    const unsigned manta = (ha << 23) | ma;         // 24-bit [hidden|mant]
    const unsigned mantb = (hb << 23) | mb;

    const bool exp_gt = (eae > ebe);
    const bool exp_eq = (eae == ebe);
    const bool mant_eq = (manta == mantb);
    const bool mant_ge = (manta >= mantb);
    const bool abs_eq  = exp_eq && mant_eq;
    const bool a_ge_b  = exp_gt || (exp_eq && mant_ge);

    const unsigned ediff = a_ge_b ? (eae - ebe) : (ebe - eae);

    // is_big_diff = (diff has any of bits>=32) OR (bit16 & bit8)  <=>  diff >= 24
    if (ediff >= 24u)
        return a_ge_b ? ra : rb;                    // larger input verbatim

    const unsigned shift = ediff;                   // < 24, low-5-bit field exact

    const unsigned Ma = manta << 4;                 // 28-bit mantissas (+4 guard)
    const unsigned Mb = mantb << 4;

    const unsigned emax = a_ge_b ? eae : ebe;
    const unsigned Ml   = a_ge_b ? Ma : Mb;
    const unsigned Ms0  = a_ge_b ? Mb : Ma;

    const bool     sticky = (Ms0 & ((1u << shift) - 1u)) != 0u;
    const unsigned Ms     = Ms0 >> shift;

    const unsigned ds = sa ^ sb;                    // is_diff_sign
    const bool exact_cancel = (ds != 0u) && abs_eq;
    const unsigned s_large = a_ge_b ? sa : sb;

    unsigned mant_res, res_carry;
    if (ds) {
        unsigned d = (Ml - Ms) & 0xFFFFFFFu;        // mod 2^28 (circuit wraps)
        if (sticky) d = (d - 1u) & 0xFFFFFFFu;      // need_sub_one
        mant_res = d;
        res_carry = 0u;
    } else {
        unsigned sum = Ml + Ms;
        res_carry = (sum >> 28) & 1u;
        mant_res = sum & 0xFFFFFFFu;
    }

    const unsigned lzc = (unsigned)__clz(mant_res) - 4u;  // 28 if zero
    const bool underflow = (lzc >= emax);                  // lzc_gt || lzc_eq
    const unsigned norm_m = (mant_res << lzc) & 0xFFFFFFFu;

    const unsigned e_after = (emax - lzc) & 0xFFu;
    const unsigned e_plus1 = (emax + 1u) & 0xFFu;
    const unsigned e_normal = underflow ? 0u : e_after;
    const unsigned final_e = res_carry ? e_plus1 : e_normal;

    unsigned m_pre, r_pre;
    bool st_raw;
    if (res_carry) {
        m_pre  = (mant_res >> 5) & 0x7FFFFFu;       // bits[0:23] of 28
        r_pre  = (mant_res >> 4) & 1u;              // bit[23]
        st_raw = (mant_res & 0xFu) != 0u;           // bits[24:28)
    } else {
        m_pre  = (norm_m >> 4) & 0x7FFFFFu;         // bits[1:24]
        r_pre  = (norm_m >> 3) & 1u;                // bit[24]
        st_raw = (norm_m & 0x7u) != 0u;             // bits[25:28)
    }
    const bool st_pre = st_raw || ((ds == 0u) && sticky);

    const unsigned m_sub = (mant_res >> 5) & 0x7FFFFFu;
    const unsigned m_sel = underflow ? m_sub : m_pre;
    const unsigned L = m_sel & 1u;

    const unsigned do_round =
        ((r_pre != 0u) && (st_pre || (L != 0u)) && !underflow) ? 1u : 0u;

    // Circuit quirk: the 24-bit round adder's carry-out is structurally 0,
    // so rounding overflow wraps mantissa to 0 WITHOUT exponent increment.
    const unsigned m_final = (m_sel + do_round) & 0x7FFFFFu;

    unsigned cs, ce, cm;
    if (exact_cancel) { cs = 0u; ce = 0u; cm = 0u; }
    else              { cs = s_large; ce = final_e; cm = m_final; }

    if (final_e == 0xFFu) {                         // computed_e all-ones override
        cs = s_large; ce = 0xFFu; cm = 0u;
    }
    return (cs << 31) | (ce << 23) | cm;
}

__global__ void __launch_bounds__(256)
spike_adder_kernel(const float* __restrict__ A,
                   const float* __restrict__ B,
                   float* __restrict__ O,
                   int nrows) {
    const int gtid = blockIdx.x * blockDim.x + threadIdx.x;
    const int row  = gtid >> 5;
    const int lane = gtid & 31;
    if (row >= nrows) return;

    const size_t base = (size_t)row * 32 + lane;
    const float av = __ldg(A + base);
    const float bv = __ldg(B + base);

    const unsigned ua = __ballot_sync(0xFFFFFFFFu, av != 0.0f);
    const unsigned ub = __ballot_sync(0xFFFFFFFFu, bv != 0.0f);
    const unsigned ra = __brev(ua);   // IEEE-layout word
    const unsigned rb = __brev(ub);

    const unsigned res = spike_fp32_add(ra, rb);

    O[base] = (float)((res >> (31 - lane)) & 1u);
}

extern "C" void kernel_launch(void* const* d_in, const int* in_sizes, int n_in,
                              void* d_out, int out_size) {
    const float* A = (const float*)d_in[0];
    const float* B = (const float*)d_in[1];
    float* O = (float*)d_out;

    const int nrows = in_sizes[0] / 32;
    const int threads = 256;
    const int warps_per_block = threads / 32;
    const int blocks = (nrows + warps_per_block - 1) / warps_per_block;

    spike_adder_kernel<<<blocks, threads>>>(A, B, O, nrows);
}

// round 2
// speedup vs baseline: 1.9384x; 1.9384x over previous
#include <cuda_runtime.h>
#include <cstdint>

// SpikeFP32Adder — integer re-implementation of the soft-gate FP32 adder.
// R2: data-parallel circuit. Each warp handles 32 rows; ballot packs each
// row's 32 {0,1} floats into a uint32 held by one lane; every lane then runs
// the (branchless) adder circuit on ITS OWN row; shfl broadcasts unpack.

__device__ __forceinline__ unsigned spike_fp32_add(unsigned ra, unsigned rb) {
    const unsigned sa = ra >> 31, sb = rb >> 31;
    const unsigned ea = (ra >> 23) & 0xFFu, eb = (rb >> 23) & 0xFFu;

    const unsigned eae = ea ? ea : 1u;                      // e_eff
    const unsigned ebe = eb ? eb : 1u;
    const unsigned manta = (ra & 0x7FFFFFu) | ((ea ? 1u : 0u) << 23);
    const unsigned mantb = (rb & 0x7FFFFFu) | ((eb ? 1u : 0u) << 23);

    const bool exp_eq = (eae == ebe);
    const bool a_ge_b = (eae > ebe) || (exp_eq && (manta >= mantb));
    const bool abs_eq = exp_eq && (manta == mantb);

    const unsigned ediff = a_ge_b ? (eae - ebe) : (ebe - eae);
    const bool big = (ediff >= 24u);                        // is_big_diff
    const unsigned shift = big ? 0u : ediff;                // keep shifts defined

    const unsigned emax = a_ge_b ? eae : ebe;
    const unsigned Ml  = (a_ge_b ? manta : mantb) << 4;     // 28-bit
    const unsigned Ms0 = (a_ge_b ? mantb : manta) << 4;

    const bool sticky = (Ms0 & ((1u << shift) - 1u)) != 0u;
    const unsigned Ms = Ms0 >> shift;

    const unsigned ds = sa ^ sb;                            // diff sign
    const bool exact_cancel = (ds != 0u) && abs_eq;
    const unsigned s_large = a_ge_b ? sa : sb;

    const unsigned sum = Ml + Ms;
    const unsigned diff = (Ml - Ms - ((ds && sticky) ? 1u : 0u)) & 0xFFFFFFFu;
    const unsigned res_carry = ds ? 0u : ((sum >> 28) & 1u);
    const unsigned mant_res = ds ? diff : (sum & 0xFFFFFFFu);

    const unsigned lzc = (unsigned)__clz(mant_res) - 4u;    // 0..28
    const bool underflow = (lzc >= emax);
    const unsigned norm_m = (mant_res << lzc) & 0xFFFFFFFu; // lzc<32, defined

    const unsigned e_after  = (emax - lzc) & 0xFFu;
    const unsigned e_plus1  = (emax + 1u) & 0xFFu;
    const unsigned e_normal = underflow ? 0u : e_after;
    const unsigned final_e  = res_carry ? e_plus1 : e_normal;

    const unsigned m_pre = res_carry ? ((mant_res >> 5) & 0x7FFFFFu)
                                     : ((norm_m  >> 4) & 0x7FFFFFu);
    const unsigned r_pre = res_carry ? ((mant_res >> 4) & 1u)
                                     : ((norm_m  >> 3) & 1u);
    const bool st_raw = res_carry ? ((mant_res & 0xFu) != 0u)
                                  : ((norm_m  & 0x7u) != 0u);
    const bool st_pre = st_raw || ((ds == 0u) && sticky);

    const unsigned m_sel = underflow ? ((mant_res >> 5) & 0x7FFFFFu) : m_pre;
    const unsigned L = m_sel & 1u;
    const unsigned do_round =
        ((r_pre != 0u) && (st_pre || (L != 0u)) && !underflow) ? 1u : 0u;

    // Round-adder carry-out is structurally 0 in the circuit: mantissa wraps
    // to 0 on rounding overflow WITHOUT exponent increment.
    const unsigned m_final = (m_sel + do_round) & 0x7FFFFFu;

    const bool inf = (final_e == 0xFFu);
    unsigned cs = exact_cancel ? 0u : s_large;
    unsigned ce = exact_cancel ? 0u : final_e;
    unsigned cm = exact_cancel ? 0u : m_final;
    cs = inf ? s_large : cs;
    ce = inf ? 0xFFu   : ce;
    cm = inf ? 0u      : cm;

    const unsigned normal = (cs << 31) | (ce << 23) | cm;
    const unsigned larger = a_ge_b ? ra : rb;
    return big ? larger : normal;
}

__global__ void __launch_bounds__(256)
spike_adder_kernel(const float* __restrict__ A,
                   const float* __restrict__ B,
                   float* __restrict__ O,
                   int nwarpTiles) {
    const int warpId = blockIdx.x * (blockDim.x >> 5) + (threadIdx.x >> 5);
    const int lane = threadIdx.x & 31;
    if (warpId >= nwarpTiles) return;

    const size_t elemBase = (size_t)warpId * 32 * 32;   // 32 rows * 32 cols
    const float* pa = A + elemBase;
    const float* pb = B + elemBase;

    unsigned ra = 0u, rb = 0u;
    #pragma unroll
    for (int i = 0; i < 32; i++) {
        const float av = __ldg(pa + i * 32 + lane);
        const float bv = __ldg(pb + i * 32 + lane);
        const unsigned ba = __ballot_sync(0xFFFFFFFFu, av != 0.0f);
        const unsigned bb = __ballot_sync(0xFFFFFFFFu, bv != 0.0f);
        if (lane == i) { ra = ba; rb = bb; }
    }
    // MSB-first bit order -> IEEE word layout
    ra = __brev(ra);
    rb = __brev(rb);

    const unsigned res = spike_fp32_add(ra, rb);        // per-lane row

    float* po = O + elemBase;
    #pragma unroll
    for (int i = 0; i < 32; i++) {
        const unsigned w = __shfl_sync(0xFFFFFFFFu, res, i);
        // bit (31-lane) of w, as float 1.0/0.0 without I2F:
        const unsigned f = ((unsigned)((int)(w << lane) >> 31)) & 0x3F800000u;
        po[i * 32 + lane] = __uint_as_float(f);
    }
}

// Scalar tail kernel (warp-per-row, original style) for nrows % 32 != 0.
__global__ void spike_adder_tail(const float* __restrict__ A,
                                 const float* __restrict__ B,
                                 float* __restrict__ O,
                                 int rowStart, int nrows) {
    const int row = rowStart + blockIdx.x;
    const int lane = threadIdx.x & 31;
    if (row >= nrows) return;
    const size_t base = (size_t)row * 32 + lane;
    const unsigned ua = __ballot_sync(0xFFFFFFFFu, A[base] != 0.0f);
    const unsigned ub = __ballot_sync(0xFFFFFFFFu, B[base] != 0.0f);
    const unsigned res = spike_fp32_add(__brev(ua), __brev(ub));
    const unsigned f = ((unsigned)((int)(res << lane) >> 31)) & 0x3F800000u;
    O[base] = __uint_as_float(f);
}

extern "C" void kernel_launch(void* const* d_in, const int* in_sizes, int n_in,
                              void* d_out, int out_size) {
    const float* A = (const float*)d_in[0];
    const float* B = (const float*)d_in[1];
    float* O = (float*)d_out;

    const int nrows = in_sizes[0] / 32;
    const int nwarpTiles = nrows / 32;                  // full 32-row tiles
    const int tailRows = nrows - nwarpTiles * 32;

    if (nwarpTiles > 0) {
        const int threads = 256;
        const int warpsPerBlock = threads / 32;
        const int blocks = (nwarpTiles + warpsPerBlock - 1) / warpsPerBlock;
        spike_adder_kernel<<<blocks, threads>>>(A, B, O, nwarpTiles);
    }
    if (tailRows > 0) {
        spike_adder_tail<<<tailRows, 32>>>(A, B, O, nwarpTiles * 32, nrows);
    }
}